// round 16
// baseline (speedup 1.0000x reference)
#include <cuda_runtime.h>
#include <math.h>

#define BB 32
#define CC 3
#define HH 512
#define WW 512
#define HW (HH * WW)
#define PI_F 3.14159f

#define NGATHER (BB * 512)          // 512 blocks per image

// ---------------------------------------------------------------------------
// Single kernel, no scratch, no handshakes. Per block, thread 0 computes
// into smem: the Heckbert closed-form homography (adjugate inverse — scale-
// free since it feeds a perspective divide), light-spot params, and the
// per-channel moire constants. Moire values are computed inline per pixel
// (2 __cosf + 1 sqrtf via MUFU, hidden in memory-stall shadows) instead of
// being staged through a 3 MB global buffer by a separate kernel.
// Gather body = measured-best R10 config: 2 px/thread, interior fast path,
// epilogue streaming with evict-streaming hints, cover folded.
// ---------------------------------------------------------------------------
__global__ void __launch_bounds__(256, 8)
main_kernel(const float* __restrict__ imgs,
            const float* __restrict__ noise,
            const float* __restrict__ cover,
            const float* __restrict__ dst_offsets,
            const float* __restrict__ hue_shift,
            const float* __restrict__ bright,
            const float* __restrict__ contrast,
            const int* __restrict__ light_xy,
            const float* __restrict__ theta,
            const float* __restrict__ center,
            float* __restrict__ out) {
    const size_t n_img = (size_t)BB * CC * HW;

    int main_id = blockIdx.x;
    int b = main_id >> 9;              // image index (512 blocks per image)
    int bx = main_id & 511;
    int p2 = (bx * 256 + threadIdx.x) * 2;
    int i = p2 >> 9;                   // row (same for both pixels)
    int j0 = p2 & (WW - 1);

    size_t base = (size_t)b * CC * HW + p2;

    // smem consts: [0:9) Minv, [9:12) light(xf,yf,1/maxlen),
    // [12:15) cx[c], [15:18) cy[c], [18:21) cos(th)[c], [21:24) sin(th)[c]
    __shared__ float sM[24];
    if (threadIdx.x == 0) {
        const float S = 512.0f;
        // src corners: k=0:(0,0) k=1:(0,S) k=2:(S,0) k=3:(S,S)
        const float sxc[4] = {0.0f, 0.0f, 512.0f, 512.0f};
        const float syc[4] = {0.0f, 512.0f, 0.0f, 512.0f};
        float du[4], dv[4];
        for (int k = 0; k < 4; k++) {
            du[k] = sxc[k] + dst_offsets[(b * 4 + k) * 2 + 0];
            dv[k] = syc[k] + dst_offsets[(b * 4 + k) * 2 + 1];
        }
        // Unit-square param: (0,0)->dst0 (1,0)->dst2 (1,1)->dst3 (0,1)->dst1
        float u0 = du[0], u1 = du[2], u2 = du[3], u3 = du[1];
        float v0 = dv[0], v1 = dv[2], v2 = dv[3], v3 = dv[1];
        float sx = u0 - u1 + u2 - u3;
        float sy = v0 - v1 + v2 - v3;
        float dx1 = u1 - u2, dx2 = u3 - u2;
        float dy1 = v1 - v2, dy2 = v3 - v2;
        float den = dx1 * dy2 - dy1 * dx2;
        float g = (sx * dy2 - sy * dx2) / den;
        float h = (dx1 * sy - dy1 * sx) / den;
        float a = u1 - u0 + g * u1;
        float bq = u3 - u0 + h * u3;
        float cc = u0;
        float d = v1 - v0 + g * v1;
        float e = v3 - v0 + h * v3;
        float f = v0;
        float m0 = a,  m1 = bq, m2 = cc * S;
        float m3 = d,  m4 = e,  m5 = f * S;
        float m6 = g,  m7 = h,  m8 = S;
        float inv9[9] = {
            m4 * m8 - m5 * m7, m2 * m7 - m1 * m8, m1 * m5 - m2 * m4,
            m5 * m6 - m3 * m8, m0 * m8 - m2 * m6, m2 * m3 - m0 * m5,
            m3 * m7 - m4 * m6, m1 * m6 - m0 * m7, m0 * m4 - m1 * m3};
        float nrm = 1.0f / inv9[8];
        for (int k = 0; k < 9; k++) sM[k] = inv9[k] * nrm;

        float xf = (float)light_xy[0];
        float yf = (float)light_xy[1];
        float d0 = sqrtf(xf * xf + yf * yf);
        float d1 = sqrtf((xf - S) * (xf - S) + yf * yf);
        float d2 = sqrtf(xf * xf + (yf - S) * (yf - S));
        float d3 = sqrtf((xf - S) * (xf - S) + (yf - S) * (yf - S));
        float ml = fmaxf(fmaxf(d0, d1), fmaxf(d2, d3)) * 0.5f;
        sM[9] = xf;
        sM[10] = yf;
        sM[11] = 1.0f / ml;

        for (int c = 0; c < 3; c++) {
            sM[12 + c] = center[c * 2 + 0];
            sM[15 + c] = center[c * 2 + 1];
            float th = theta[c] / 180.0f * PI_F;
            sM[18 + c] = __cosf(th);
            sM[21 + c] = __sinf(th);
        }
    }
    __syncthreads();

    // Projective map (row-constant parts hoisted).
    float y = (float)i;
    float cA = sM[1] * y + sM[2];
    float cB = sM[4] * y + sM[5];
    float cW = sM[7] * y + sM[8];

    int ix0[2], iy0[2];
    float wx[2], wy[2];
    bool interior = true;
#pragma unroll
    for (int q = 0; q < 2; q++) {
        float x = (float)(j0 + q);
        float invw = __fdividef(1.0f, sM[6] * x + cW);
        float sxv = (sM[0] * x + cA) * invw;
        float syv = (sM[3] * x + cB) * invw;
        float x0f = floorf(sxv), y0f = floorf(syv);
        wx[q] = sxv - x0f;
        wy[q] = syv - y0f;
        ix0[q] = (int)x0f;
        iy0[q] = (int)y0f;
        interior &= ((unsigned)ix0[q] <= (unsigned)(WW - 2)) &&
                    ((unsigned)iy0[q] <= (unsigned)(HH - 2));
    }

    float ct = contrast[b];
    float br = bright[b];

    const float* imb = imgs + (size_t)b * CC * HW;
    float v[3][2];
    if (interior) {
        // Fast path: all taps in-bounds, raw indices, no masks.
        int o00[2];
#pragma unroll
        for (int q = 0; q < 2; q++) o00[q] = iy0[q] * WW + ix0[q];
#pragma unroll
        for (int c = 0; c < 3; c++) {
            const float* im = imb + c * HW;
            float hs = hue_shift[b * 3 + c];
#pragma unroll
            for (int q = 0; q < 2; q++) {
                float v00 = im[o00[q]];
                float v01 = im[o00[q] + 1];
                float v10 = im[o00[q] + WW];
                float v11 = im[o00[q] + WW + 1];
                float top = v00 + wx[q] * (v01 - v00);
                float bot = v10 + wx[q] * (v11 - v10);
                float val = top + wy[q] * (bot - top);
                float o = val * ct + hs + br;
                v[c][q] = fminf(fmaxf(o, -1.0f), 1.0f);
            }
        }
    } else {
        // Boundary path: kornia zero-padding semantics (mask, clamp).
#pragma unroll
        for (int c = 0; c < 3; c++) {
            const float* im = imb + c * HW;
            float hs = hue_shift[b * 3 + c];
#pragma unroll
            for (int q = 0; q < 2; q++) {
                int x0 = ix0[q], y0 = iy0[q];
                int x1 = x0 + 1, y1 = y0 + 1;
                bool vx0 = (x0 >= 0) && (x0 < WW);
                bool vx1 = (x1 >= 0) && (x1 < WW);
                bool vy0 = (y0 >= 0) && (y0 < HH);
                bool vy1 = (y1 >= 0) && (y1 < HH);
                int cx0 = min(max(x0, 0), WW - 1);
                int cx1 = min(max(x1, 0), WW - 1);
                int cy0 = min(max(y0, 0), HH - 1) * WW;
                int cy1 = min(max(y1, 0), HH - 1) * WW;
                float v00 = (vy0 && vx0) ? im[cy0 + cx0] : 0.0f;
                float v01 = (vy0 && vx1) ? im[cy0 + cx1] : 0.0f;
                float v10 = (vy1 && vx0) ? im[cy1 + cx0] : 0.0f;
                float v11 = (vy1 && vx1) ? im[cy1 + cx1] : 0.0f;
                float val = (1.0f - wy[q]) * ((1.0f - wx[q]) * v00 + wx[q] * v01) +
                            wy[q] * ((1.0f - wx[q]) * v10 + wx[q] * v11);
                float o = val * ct + hs + br;
                v[c][q] = fminf(fmaxf(o, -1.0f), 1.0f);
            }
        }
    }

    // light spot (row-constant di)
    float xf = sM[9], yf = sM[10], rml = sM[11];
    float di = (float)i - xf;
    float di2 = di * di;

    float lum[2], light[2];
#pragma unroll
    for (int q = 0; q < 2; q++) {
        lum[q] = (0.3f * v[0][q] + 0.6f * v[1][q] + 0.1f * v[2][q]) *
                 (1.0f / 3.0f);
        float dj = (float)(j0 + q) - yf;
        float dl = sqrtf(di2 + dj * dj);
        float lw = 1.0f - dl * rml;
        light[q] = (lw > 0.0f) ? lw : 0.0f;
    }

    // Epilogue: moire computed inline (MUFU, hidden in mem-stall shadows);
    // streaming loads/stores with evict-streaming hints (no L2 reuse).
    const float kn = 0.031622776601683794f;  // sqrt(0.001)
    float fi = (float)i;
#pragma unroll
    for (int c = 0; c < 3; c++) {
        size_t off = base + (size_t)c * HW;
        float2 nz = __ldcs(reinterpret_cast<const float2*>(noise + off));
        float2 cv = __ldcs(reinterpret_cast<const float2*>(cover + off));

        float dxm = fi - sM[12 + c];
        float dxm2 = dxm * dxm;
        float si = sM[21 + c] * fi;
        float cth = sM[18 + c];
        float cym = sM[15 + c];

        float mo[2];
#pragma unroll
        for (int q = 0; q < 2; q++) {
            float jj = (float)(j0 + q);
            float dym = jj - cym;
            float z1 = 0.5f + 0.5f * __cosf(2.0f * PI_F *
                                            sqrtf(dxm2 + dym * dym));
            float z2 = 0.5f + 0.5f * __cosf(cth * jj + si);
            mo[q] = fminf(z1, z2) * 2.0f - 1.0f;
        }

        float2 o2;
        o2.x = 0.7f * v[c][0] + 0.3f * lum[0] + light[0] + mo[0] * 0.2f +
               kn * nz.x;
        o2.y = 0.7f * v[c][1] + 0.3f * lum[1] + light[1] + mo[1] * 0.2f +
               kn * nz.y;
        __stcs(reinterpret_cast<float2*>(out + off), o2);
        __stcs(reinterpret_cast<float2*>(out + n_img + off), cv);
    }
}

// ---------------------------------------------------------------------------
// Inputs (metadata order): 0 imgs, 1 cover, 2 dst_offsets, 3 hue_shift,
// 4 bright, 5 contrast, 6 light_xy(int32), 7 moire_theta, 8 moire_center,
// 9 noise. Output: [noised | cover], 2 * 32*3*512*512 floats.
// ---------------------------------------------------------------------------
extern "C" void kernel_launch(void* const* d_in, const int* in_sizes, int n_in,
                              void* d_out, int out_size) {
    const float* imgs        = (const float*)d_in[0];
    const float* cover       = (const float*)d_in[1];
    const float* dst_offsets = (const float*)d_in[2];
    const float* hue_shift   = (const float*)d_in[3];
    const float* bright      = (const float*)d_in[4];
    const float* contrast    = (const float*)d_in[5];
    const int*   light_xy    = (const int*)d_in[6];
    const float* moire_theta = (const float*)d_in[7];
    const float* moire_cent  = (const float*)d_in[8];
    const float* noise       = (const float*)d_in[9];
    float* out = (float*)d_out;

    main_kernel<<<NGATHER, 256>>>(imgs, noise, cover, dst_offsets, hue_shift,
                                  bright, contrast, light_xy, moire_theta,
                                  moire_cent, out);
}

// round 17
// speedup vs baseline: 1.0426x; 1.0426x over previous
#include <cuda_runtime.h>
#include <math.h>

#define BB 32
#define CC 3
#define HH 512
#define WW 512
#define HW (HH * WW)
#define PI_F 3.14159f

// Scratch: per-batch inverse homographies, light params, batch-invariant
// moire field (3 MB, L2-resident, reused 32x — computing it ONCE here and
// amortizing beats inlining it 32x in the main kernel by ~10 us, measured).
__device__ float g_minv[BB][9];
__device__ float g_light[3];   // xf, yf, 1/max_len
__device__ float g_moire[CC * HW];

// ---------------------------------------------------------------------------
// Prep: moire field (4 px/thread, float4 stores, fast-math cos) + block-0
// side jobs: closed-form (Heckbert) homography per batch in fp32 and light
// params. Homography is unique up to scale and only used through a
// perspective divide, so the adjugate (un-normalized inverse) suffices.
// ---------------------------------------------------------------------------
__global__ void prep_kernel(const float* __restrict__ theta,
                            const float* __restrict__ center,
                            const float* __restrict__ dst_offsets,
                            const int* __restrict__ light_xy) {
    if (blockIdx.x == 0) {
        int b = threadIdx.x;
        if (b == 32) {
            float xf = (float)light_xy[0];
            float yf = (float)light_xy[1];
            const float S = 512.0f;
            float d0 = sqrtf(xf * xf + yf * yf);
            float d1 = sqrtf((xf - S) * (xf - S) + yf * yf);
            float d2 = sqrtf(xf * xf + (yf - S) * (yf - S));
            float d3 = sqrtf((xf - S) * (xf - S) + (yf - S) * (yf - S));
            float ml = fmaxf(fmaxf(d0, d1), fmaxf(d2, d3)) * 0.5f;
            g_light[0] = xf;
            g_light[1] = yf;
            g_light[2] = 1.0f / ml;
        }
        if (b < BB) {
            const float S = 512.0f;
            // src corners: k=0:(0,0) k=1:(0,S) k=2:(S,0) k=3:(S,S)
            const float sxc[4] = {0.0f, 0.0f, 512.0f, 512.0f};
            const float syc[4] = {0.0f, 512.0f, 0.0f, 512.0f};
            float du[4], dv[4];
            for (int k = 0; k < 4; k++) {
                du[k] = sxc[k] + dst_offsets[(b * 4 + k) * 2 + 0];
                dv[k] = syc[k] + dst_offsets[(b * 4 + k) * 2 + 1];
            }
            // Unit-square param: (0,0)->dst0 (1,0)->dst2 (1,1)->dst3 (0,1)->dst1
            float u0 = du[0], u1 = du[2], u2 = du[3], u3 = du[1];
            float v0 = dv[0], v1 = dv[2], v2 = dv[3], v3 = dv[1];
            float sx = u0 - u1 + u2 - u3;
            float sy = v0 - v1 + v2 - v3;
            float dx1 = u1 - u2, dx2 = u3 - u2;
            float dy1 = v1 - v2, dy2 = v3 - v2;
            float den = dx1 * dy2 - dy1 * dx2;
            float g = (sx * dy2 - sy * dx2) / den;
            float h = (dx1 * sy - dy1 * sx) / den;
            float a = u1 - u0 + g * u1;
            float bq = u3 - u0 + h * u3;
            float c = u0;
            float d = v1 - v0 + g * v1;
            float e = v3 - v0 + h * v3;
            float f = v0;
            float m0 = a,  m1 = bq, m2 = c * S;
            float m3 = d,  m4 = e,  m5 = f * S;
            float m6 = g,  m7 = h,  m8 = S;
            float inv9[9] = {
                m4 * m8 - m5 * m7, m2 * m7 - m1 * m8, m1 * m5 - m2 * m4,
                m5 * m6 - m3 * m8, m0 * m8 - m2 * m6, m2 * m3 - m0 * m5,
                m3 * m7 - m4 * m6, m1 * m6 - m0 * m7, m0 * m4 - m1 * m3};
            float nrm = 1.0f / inv9[8];
            for (int k = 0; k < 9; k++) g_minv[b][k] = inv9[k] * nrm;
        }
    }

    int idx4 = (blockIdx.x * blockDim.x + threadIdx.x) * 4;
    if (idx4 >= CC * HW) return;
    int c = idx4 / HW;
    int rem = idx4 - c * HW;
    int i = rem >> 9;
    int j0 = rem & (WW - 1);   // 4-aligned, all 4 cols in same row

    float cx = center[c * 2 + 0];
    float cy = center[c * 2 + 1];
    float th = theta[c] / 180.0f * PI_F;
    float cth = __cosf(th), sth = __sinf(th);
    float dx = (float)i - cx;
    float dx2 = dx * dx;
    float si = sth * (float)i;

    float4 m4v;
    float* mp = &m4v.x;
#pragma unroll
    for (int q = 0; q < 4; q++) {
        float jj = (float)(j0 + q);
        float dy = jj - cy;
        float z1 = 0.5f + 0.5f * __cosf(2.0f * PI_F * sqrtf(dx2 + dy * dy));
        float z2 = 0.5f + 0.5f * __cosf(cth * jj + si);
        mp[q] = fminf(z1, z2) * 2.0f - 1.0f;
    }
    *reinterpret_cast<float4*>(g_moire + idx4) = m4v;
}

// ---------------------------------------------------------------------------
// Fused main kernel (timed-best R9 configuration): 2 px/thread, float2
// streaming I/O in the PROLOGUE (per-thread MLP; 40 regs, 6 blocks/SM),
// interior fast path, evict-streaming hints, cover pass-through folded.
// ---------------------------------------------------------------------------
__global__ void __launch_bounds__(256, 6)
main_kernel(const float* __restrict__ imgs,
            const float* __restrict__ noise,
            const float* __restrict__ cover,
            const float* __restrict__ hue_shift,
            const float* __restrict__ bright,
            const float* __restrict__ contrast,
            float* __restrict__ out) {
    int t = blockIdx.x * blockDim.x + threadIdx.x;
    int p2 = t * 2;                 // first pixel of the pair
    if (p2 >= HW) return;
    int b = blockIdx.y;
    int i = p2 >> 9;                // row (same for both pixels)
    int j0 = p2 & (WW - 1);

    const size_t n_img = (size_t)BB * CC * HW;
    size_t base = (size_t)b * CC * HW + p2;

    // Streaming loads first (independent of the gather chain; no L2 reuse ->
    // evict-streaming policy).
    float2 nz[3], cv[3], mo[3];
#pragma unroll
    for (int c = 0; c < 3; c++) {
        nz[c] = __ldcs(reinterpret_cast<const float2*>(noise + base + (size_t)c * HW));
        cv[c] = __ldcs(reinterpret_cast<const float2*>(cover + base + (size_t)c * HW));
        mo[c] = __ldg(reinterpret_cast<const float2*>(g_moire + c * HW + p2));
    }

    // Projective map (row-constant parts hoisted).
    const float* mv = g_minv[b];
    float y = (float)i;
    float cA = mv[1] * y + mv[2];
    float cB = mv[4] * y + mv[5];
    float cW = mv[7] * y + mv[8];

    int ix0[2], iy0[2];
    float wx[2], wy[2];
    bool interior = true;
#pragma unroll
    for (int q = 0; q < 2; q++) {
        float x = (float)(j0 + q);
        float invw = __fdividef(1.0f, mv[6] * x + cW);
        float sxv = (mv[0] * x + cA) * invw;
        float syv = (mv[3] * x + cB) * invw;
        float x0f = floorf(sxv), y0f = floorf(syv);
        wx[q] = sxv - x0f;
        wy[q] = syv - y0f;
        ix0[q] = (int)x0f;
        iy0[q] = (int)y0f;
        interior &= ((unsigned)ix0[q] <= (unsigned)(WW - 2)) &&
                    ((unsigned)iy0[q] <= (unsigned)(HH - 2));
    }

    float ct = contrast[b];
    float br = bright[b];
    float hs0 = hue_shift[b * 3 + 0];
    float hs1 = hue_shift[b * 3 + 1];
    float hs2 = hue_shift[b * 3 + 2];

    const float* imb = imgs + (size_t)b * CC * HW;
    float v[3][2];
    if (interior) {
        // Fast path: all taps in-bounds, raw indices, no masks.
        int o00[2], o10[2];
#pragma unroll
        for (int q = 0; q < 2; q++) {
            o00[q] = iy0[q] * WW + ix0[q];
            o10[q] = o00[q] + WW;
        }
#pragma unroll
        for (int c = 0; c < 3; c++) {
            const float* im = imb + c * HW;
            float hs = (c == 0) ? hs0 : ((c == 1) ? hs1 : hs2);
#pragma unroll
            for (int q = 0; q < 2; q++) {
                float v00 = im[o00[q]];
                float v01 = im[o00[q] + 1];
                float v10 = im[o10[q]];
                float v11 = im[o10[q] + 1];
                float top = v00 + wx[q] * (v01 - v00);
                float bot = v10 + wx[q] * (v11 - v10);
                float val = top + wy[q] * (bot - top);
                float o = val * ct + hs + br;
                v[c][q] = fminf(fmaxf(o, -1.0f), 1.0f);
            }
        }
    } else {
        // Boundary path: kornia zero-padding semantics (mask, clamp).
#pragma unroll
        for (int c = 0; c < 3; c++) {
            const float* im = imb + c * HW;
            float hs = (c == 0) ? hs0 : ((c == 1) ? hs1 : hs2);
#pragma unroll
            for (int q = 0; q < 2; q++) {
                int x0 = ix0[q], y0 = iy0[q];
                int x1 = x0 + 1, y1 = y0 + 1;
                bool vx0 = (x0 >= 0) && (x0 < WW);
                bool vx1 = (x1 >= 0) && (x1 < WW);
                bool vy0 = (y0 >= 0) && (y0 < HH);
                bool vy1 = (y1 >= 0) && (y1 < HH);
                int cx0 = min(max(x0, 0), WW - 1);
                int cx1 = min(max(x1, 0), WW - 1);
                int cy0 = min(max(y0, 0), HH - 1) * WW;
                int cy1 = min(max(y1, 0), HH - 1) * WW;
                float v00 = (vy0 && vx0) ? im[cy0 + cx0] : 0.0f;
                float v01 = (vy0 && vx1) ? im[cy0 + cx1] : 0.0f;
                float v10 = (vy1 && vx0) ? im[cy1 + cx0] : 0.0f;
                float v11 = (vy1 && vx1) ? im[cy1 + cx1] : 0.0f;
                float val = (1.0f - wy[q]) * ((1.0f - wx[q]) * v00 + wx[q] * v01) +
                            wy[q] * ((1.0f - wx[q]) * v10 + wx[q] * v11);
                float o = val * ct + hs + br;
                v[c][q] = fminf(fmaxf(o, -1.0f), 1.0f);
            }
        }
    }

    // light spot (row-constant di)
    float xf = g_light[0], yf = g_light[1], rml = g_light[2];
    float di = (float)i - xf;
    float di2 = di * di;

    float lum[2], light[2];
#pragma unroll
    for (int q = 0; q < 2; q++) {
        lum[q] = (0.3f * v[0][q] + 0.6f * v[1][q] + 0.1f * v[2][q]) *
                 (1.0f / 3.0f);
        float dj = (float)(j0 + q) - yf;
        float dl = sqrtf(di2 + dj * dj);
        float lw = 1.0f - dl * rml;
        light[q] = (lw > 0.0f) ? lw : 0.0f;
    }

    const float kn = 0.031622776601683794f;  // sqrt(0.001)
#pragma unroll
    for (int c = 0; c < 3; c++) {
        float2 o2;
        o2.x = 0.7f * v[c][0] + 0.3f * lum[0] + light[0] + mo[c].x * 0.2f +
               kn * nz[c].x;
        o2.y = 0.7f * v[c][1] + 0.3f * lum[1] + light[1] + mo[c].y * 0.2f +
               kn * nz[c].y;
        size_t off = base + (size_t)c * HW;
        __stcs(reinterpret_cast<float2*>(out + off), o2);
        __stcs(reinterpret_cast<float2*>(out + n_img + off), cv[c]);
    }
}

// ---------------------------------------------------------------------------
// Inputs (metadata order): 0 imgs, 1 cover, 2 dst_offsets, 3 hue_shift,
// 4 bright, 5 contrast, 6 light_xy(int32), 7 moire_theta, 8 moire_center,
// 9 noise. Output: [noised | cover], 2 * 32*3*512*512 floats.
// ---------------------------------------------------------------------------
extern "C" void kernel_launch(void* const* d_in, const int* in_sizes, int n_in,
                              void* d_out, int out_size) {
    const float* imgs        = (const float*)d_in[0];
    const float* cover       = (const float*)d_in[1];
    const float* dst_offsets = (const float*)d_in[2];
    const float* hue_shift   = (const float*)d_in[3];
    const float* bright      = (const float*)d_in[4];
    const float* contrast    = (const float*)d_in[5];
    const int*   light_xy    = (const int*)d_in[6];
    const float* moire_theta = (const float*)d_in[7];
    const float* moire_cent  = (const float*)d_in[8];
    const float* noise       = (const float*)d_in[9];
    float* out = (float*)d_out;

    prep_kernel<<<(CC * HW + 1023) / 1024, 256>>>(moire_theta, moire_cent,
                                                  dst_offsets, light_xy);

    dim3 grid(HW / (256 * 2), BB);
    main_kernel<<<grid, 256>>>(imgs, noise, cover, hue_shift, bright, contrast,
                               out);
}